// round 15
// baseline (speedup 1.0000x reference)
#include <cuda_runtime.h>
#include <cuda_fp16.h>
#include <cstdint>

// ---------------------------------------------------------------------------
// Problem constants
// ---------------------------------------------------------------------------
#define NMAX 50000
#define EMAX 800000
#define DIN  256
#define DHID 256
#define DOUT 128

// ---------------------------------------------------------------------------
// Device scratch
// ---------------------------------------------------------------------------
__device__ __half g_featA[(size_t)NMAX * DHID];   // layer-1 GEMM outputs
__device__ __half g_featB[(size_t)NMAX * DHID];
__device__ __half g_featC[(size_t)NMAX * DHID];
__device__ __half g_feat2A[(size_t)NMAX * DOUT];  // layer-2 GEMM outputs
__device__ __half g_feat2B[(size_t)NMAX * DOUT];
__device__ __half g_feat2C[(size_t)NMAX * DOUT];
__device__ __half g_hu16[(size_t)NMAX * DHID];
__device__ __half g_hi16[(size_t)NMAX * DHID];
__device__ __half g_xu16[(size_t)NMAX * DIN];
__device__ __half g_xi16[(size_t)NMAX * DIN];
__device__ __half g_w16 [3 * 256 * 256 + 3 * 128 * 256];  // transposed fp16 weights
__device__ int    g_deg [6 * NMAX];   // 0/2/4: out-deg F/R/RB, 1/3/5: in-deg F/R/RB
__device__ float  g_rsq [6 * NMAX];
__device__ int    g_csr_ptr[3 * NMAX];
__device__ int    g_csr_src[3 * EMAX];

// weight slot offsets in g_w16
#define W16_1F   0
#define W16_1R   (256 * 256)
#define W16_1RB  (2 * 256 * 256)
#define W16_2F   (3 * 256 * 256)
#define W16_2R   (3 * 256 * 256 + 128 * 256)
#define W16_2RB  (3 * 256 * 256 + 2 * 128 * 256)

// ---------------------------------------------------------------------------
// Streams/events (static-init, before harness mem checkpoints)
// ---------------------------------------------------------------------------
namespace {
struct Ctx {
    cudaStream_t sC, s1, s2, s3;
    cudaEvent_t evRoot, evXU, evG1f, evDeg, evScan, evPF, evPR, evPRB,
                evW2, evHU0, evHU1, evHI0, evHI1, evG2f, evU2, evI2;
    Ctx() {
        int lo = 0, hi = 0;
        cudaDeviceGetStreamPriorityRange(&lo, &hi);
        cudaStreamCreateWithPriority(&s1, cudaStreamNonBlocking, hi);
        cudaStreamCreateWithPriority(&s2, cudaStreamNonBlocking, hi);
        cudaStreamCreateWithPriority(&sC, cudaStreamNonBlocking, lo);
        cudaStreamCreateWithPriority(&s3, cudaStreamNonBlocking, lo);
        cudaEvent_t* evs[16] = {&evRoot, &evXU, &evG1f, &evDeg, &evScan,
                                &evPF, &evPR, &evPRB, &evW2, &evHU0, &evHU1,
                                &evHI0, &evHI1, &evG2f, &evU2, &evI2};
        for (int i = 0; i < 16; i++)
            cudaEventCreateWithFlags(evs[i], cudaEventDisableTiming);
    }
};
Ctx g_ctx;
}

// ---------------------------------------------------------------------------
// fp32 -> fp16 converters
// ---------------------------------------------------------------------------
__global__ void cvtX_kernel(const float* __restrict__ in, __half* __restrict__ out, int n4)
{
    int i = blockIdx.x * blockDim.x + threadIdx.x;
    if (i < n4) {
        float4 v = ((const float4*)in)[i];
        __half2 h0 = __floats2half2_rn(v.x, v.y);
        __half2 h1 = __floats2half2_rn(v.z, v.w);
        uint2 u;
        u.x = *(uint32_t*)&h0;
        u.y = *(uint32_t*)&h1;
        ((uint2*)out)[i] = u;
    }
}

// W [256 x N_] fp32 row-major  ->  Wt [N_ x 256] fp16 (k contiguous)
template<int N_>
__global__ void cvtW_kernel(const float* __restrict__ in, __half* __restrict__ out)
{
    int i = blockIdx.x * blockDim.x + threadIdx.x;
    if (i < N_ * 256) {
        int n = i >> 8;
        int k = i & 255;
        out[i] = __float2half(in[k * N_ + n]);
    }
}

// ---------------------------------------------------------------------------
// Degrees: all 3 relations in one pass
// ---------------------------------------------------------------------------
__global__ void deg3_kernel(const int* __restrict__ sF, const int* __restrict__ dF,
                            const int* __restrict__ sR, const int* __restrict__ dR,
                            const int* __restrict__ sRB, const int* __restrict__ dRB,
                            int* __restrict__ deg, int E)
{
    int i = blockIdx.x * blockDim.x + threadIdx.x;
    if (i < E) {
        atomicAdd(&deg[0 * NMAX + sF[i]],  1);
        atomicAdd(&deg[1 * NMAX + dF[i]],  1);
        atomicAdd(&deg[2 * NMAX + sR[i]],  1);
        atomicAdd(&deg[3 * NMAX + dR[i]],  1);
        atomicAdd(&deg[4 * NMAX + sRB[i]], 1);
        atomicAdd(&deg[5 * NMAX + dRB[i]], 1);
    }
}

__global__ void rsq_kernel(const int* __restrict__ deg, float* __restrict__ rsq, int n)
{
    int i = blockIdx.x * blockDim.x + threadIdx.x;
    if (i < n) rsq[i] = rsqrtf(fmaxf((float)deg[i], 1.0f));
}

// ---------------------------------------------------------------------------
// Exclusive scan of the 3 in-degree histograms -> csr_ptr. One block per rel.
// ---------------------------------------------------------------------------
__global__ __launch_bounds__(1024)
void scan3_kernel(const int* __restrict__ deg, int* __restrict__ csr_ptr)
{
    const int rel = blockIdx.x;
    const int* c = deg + (2 * rel + 1) * NMAX;
    int* p = csr_ptr + rel * NMAX;
    __shared__ int wtot[32];
    __shared__ int carry;
    const int tid = threadIdx.x, lane = tid & 31, wid = tid >> 5;
    if (tid == 0) carry = 0;
    __syncthreads();
    for (int base = 0; base < NMAX; base += 1024) {
        int i = base + tid;
        int v = (i < NMAX) ? c[i] : 0;
        int x = v;
        #pragma unroll
        for (int d = 1; d < 32; d <<= 1) {
            int y = __shfl_up_sync(0xffffffffu, x, d);
            if (lane >= d) x += y;
        }
        if (lane == 31) wtot[wid] = x;
        __syncthreads();
        if (wid == 0) {
            int t = wtot[lane];
            #pragma unroll
            for (int d = 1; d < 32; d <<= 1) {
                int y = __shfl_up_sync(0xffffffffu, t, d);
                if (lane >= d) t += y;
            }
            wtot[lane] = t;
        }
        __syncthreads();
        int base_w = (wid == 0) ? 0 : wtot[wid - 1];
        if (i < NMAX) p[i] = carry + base_w + x - v;
        __syncthreads();
        if (tid == 0) carry += wtot[31];
        __syncthreads();
    }
}

__global__ void place_kernel(const int* __restrict__ src, const int* __restrict__ dst,
                             int* __restrict__ ptr, int* __restrict__ outsrc, int E)
{
    int i = blockIdx.x * blockDim.x + threadIdx.x;
    if (i < E) {
        int p = atomicAdd(&ptr[dst[i]], 1);
        outsrc[p] = src[i];
    }
}

// ---------------------------------------------------------------------------
// cp.async helper (16B, zero-fill when pred false)
// ---------------------------------------------------------------------------
__device__ __forceinline__ void cp16(uint32_t saddr, const void* gptr, bool pred)
{
    int sz = pred ? 16 : 0;
    asm volatile("cp.async.ca.shared.global [%0], [%1], 16, %2;"
                 :: "r"(saddr), "l"(gptr), "r"(sz));
}

__device__ __forceinline__ void ldsm_x4(uint32_t addr, uint32_t& r0, uint32_t& r1,
                                        uint32_t& r2, uint32_t& r3)
{
    asm volatile("ldmatrix.sync.aligned.m8n8.x4.shared.b16 {%0,%1,%2,%3}, [%4];"
                 : "=r"(r0), "=r"(r1), "=r"(r2), "=r"(r3) : "r"(addr));
}

// ---------------------------------------------------------------------------
// FP16 tensor-core GEMM (fp32 accumulate), cp.async double-buffered, LDSM
// fragment loads:  C[M x N] (fp16) = A[M x 256] (fp16) @ Wt[N x 256]^T (fp16)
// BM=128, BN=64, BK=64; 8 warps (4M x 2N), 32x32 warp tile, m16n8k16.
// Stride 72 halves: every 8-row LDSM phase covers all 32 banks once.
// ---------------------------------------------------------------------------
template<int N>
__global__ __launch_bounds__(256)
void gemm_f16(const __half* __restrict__ A, const __half* __restrict__ Wt,
              __half* __restrict__ C, int M)
{
    constexpr int K = 256, BM = 128, BK = 64;
    constexpr int STR = 72;                 // halves
    constexpr int ABUF = BM * STR;
    constexpr int BBUF = 64 * STR;
    extern __shared__ __half sm[];
    __half* As = sm;
    __half* Bs = sm + 2 * ABUF;

    const int tid  = threadIdx.x;
    const int warp = tid >> 5;
    const int lane = tid & 31;
    const int wm = (warp >> 1) * 32;
    const int wn = (warp & 1) * 32;
    const int row0 = blockIdx.x * BM;
    const int col0 = blockIdx.y * 64;

    const int arow = tid >> 1;
    const int aseg = (tid & 1) * 32;
    const bool aok = (row0 + arow) < M;
    const __half* agp = A + (size_t)(aok ? row0 + arow : 0) * K + aseg;
    const int brow = tid >> 2;
    const int bseg = (tid & 3) * 16;
    const __half* bgp = Wt + (size_t)(col0 + brow) * K + bseg;

    auto stage = [&](int buf, int k0) {
        uint32_t as = (uint32_t)__cvta_generic_to_shared(
            &As[buf * ABUF + arow * STR + aseg]);
        const __half* ag = agp + k0;
        #pragma unroll
        for (int j = 0; j < 4; j++) cp16(as + j * 16, ag + j * 8, aok);
        uint32_t bs = (uint32_t)__cvta_generic_to_shared(
            &Bs[buf * BBUF + brow * STR + bseg]);
        const __half* bg = bgp + k0;
        #pragma unroll
        for (int j = 0; j < 2; j++) cp16(bs + j * 16, bg + j * 8, true);
    };

    // LDSM lane address components (in halves, relative to tile base)
    const int laneA_off = (wm + (lane & 15)) * STR + ((lane & 16) ? 8 : 0);
    const int laneB_off = (wn + (lane & 7) + ((lane & 16) ? 8 : 0)) * STR
                        + ((lane & 8) ? 8 : 0);

    const uint32_t AsS = (uint32_t)__cvta_generic_to_shared(As);
    const uint32_t BsS = (uint32_t)__cvta_generic_to_shared(Bs);

    stage(0, 0);
    asm volatile("cp.async.commit_group;");

    float acc[2][4][4] = {};

    #pragma unroll
    for (int t = 0; t < K / BK; t++) {
        int buf = t & 1;
        if (t + 1 < K / BK) stage(buf ^ 1, (t + 1) * BK);
        asm volatile("cp.async.commit_group;");
        asm volatile("cp.async.wait_group 1;");
        __syncthreads();

        const uint32_t AbS = AsS + (uint32_t)(buf * ABUF) * 2 + (uint32_t)laneA_off * 2;
        const uint32_t BbS = BsS + (uint32_t)(buf * BBUF) * 2 + (uint32_t)laneB_off * 2;
        #pragma unroll
        for (int ks = 0; ks < BK; ks += 16) {
            uint32_t a[2][4];
            #pragma unroll
            for (int mt = 0; mt < 2; mt++)
                ldsm_x4(AbS + (uint32_t)(mt * 16 * STR + ks) * 2,
                        a[mt][0], a[mt][1], a[mt][2], a[mt][3]);
            uint32_t b[4][2];
            #pragma unroll
            for (int ntp = 0; ntp < 4; ntp += 2)
                ldsm_x4(BbS + (uint32_t)(ntp * 8 * STR + ks) * 2,
                        b[ntp][0], b[ntp][1], b[ntp + 1][0], b[ntp + 1][1]);
            #pragma unroll
            for (int mt = 0; mt < 2; mt++)
                #pragma unroll
                for (int nt = 0; nt < 4; nt++) {
                    asm volatile(
                        "mma.sync.aligned.m16n8k16.row.col.f32.f16.f16.f32 "
                        "{%0,%1,%2,%3}, {%4,%5,%6,%7}, {%8,%9}, {%0,%1,%2,%3};"
                        : "+f"(acc[mt][nt][0]), "+f"(acc[mt][nt][1]),
                          "+f"(acc[mt][nt][2]), "+f"(acc[mt][nt][3])
                        : "r"(a[mt][0]), "r"(a[mt][1]), "r"(a[mt][2]), "r"(a[mt][3]),
                          "r"(b[nt][0]), "r"(b[nt][1]));
                }
        }
        __syncthreads();
    }

    #pragma unroll
    for (int mt = 0; mt < 2; mt++) {
        int r0g = row0 + wm + mt * 16 + (lane >> 2);
        int r1g = r0g + 8;
        #pragma unroll
        for (int nt = 0; nt < 4; nt++) {
            int cg = col0 + wn + nt * 8 + 2 * (lane & 3);
            if (r0g < M) {
                __half2 h = __floats2half2_rn(acc[mt][nt][0], acc[mt][nt][1]);
                *(__half2*)(C + (size_t)r0g * N + cg) = h;
            }
            if (r1g < M) {
                __half2 h = __floats2half2_rn(acc[mt][nt][2], acc[mt][nt][3]);
                *(__half2*)(C + (size_t)r1g * N + cg) = h;
            }
        }
    }
}

// ---------------------------------------------------------------------------
// One fp16 row accumulate
// ---------------------------------------------------------------------------
template<int H>
__device__ __forceinline__ void acc_row(const __half* __restrict__ feat,
                                        int s, float w, int lane, float acc[H])
{
    constexpr int D = H * 32;
    const __half* r = feat + (size_t)s * D + lane * H;
    if (H == 8) {
        uint4 u = __ldg((const uint4*)r);
        float2 f0 = __half22float2(*(__half2*)&u.x);
        float2 f1 = __half22float2(*(__half2*)&u.y);
        float2 f2 = __half22float2(*(__half2*)&u.z);
        float2 f3 = __half22float2(*(__half2*)&u.w);
        acc[0] += w * f0.x; acc[1] += w * f0.y;
        acc[2] += w * f1.x; acc[3] += w * f1.y;
        acc[4] += w * f2.x; acc[5] += w * f2.y;
        acc[6] += w * f3.x; acc[7] += w * f3.y;
    } else {
        uint2 u = __ldg((const uint2*)r);
        float2 f0 = __half22float2(*(__half2*)&u.x);
        float2 f1 = __half22float2(*(__half2*)&u.y);
        acc[0] += w * f0.x; acc[1] += w * f0.y;
        acc[2] += w * f1.x; acc[3] += w * f1.y;
    }
}

template<int H>
__device__ __forceinline__ void gather_rel(
    const __half* __restrict__ feat, const int* __restrict__ src,
    const float* __restrict__ rsqOut, int beg, int end, int lane, float acc[H])
{
    int e = beg;
    for (; e + 4 <= end; e += 4) {
        int s0 = __ldg(&src[e]);
        int s1 = __ldg(&src[e + 1]);
        int s2 = __ldg(&src[e + 2]);
        int s3 = __ldg(&src[e + 3]);
        float w0 = __ldg(&rsqOut[s0]);
        float w1 = __ldg(&rsqOut[s1]);
        float w2 = __ldg(&rsqOut[s2]);
        float w3 = __ldg(&rsqOut[s3]);
        acc_row<H>(feat, s0, w0, lane, acc);
        acc_row<H>(feat, s1, w1, lane, acc);
        acc_row<H>(feat, s2, w2, lane, acc);
        acc_row<H>(feat, s3, w3, lane, acc);
    }
    for (; e < end; e++) {
        int s = __ldg(&src[e]);
        float w = __ldg(&rsqOut[s]);
        acc_row<H>(feat, s, w, lane, acc);
    }
}

// ---------------------------------------------------------------------------
// Gather-SpMM (fp16 features), fused epilogue. One warp per dst row.
// Processes rows [rowBeg, rowEnd) for cross-layer chunked pipelining.
// ---------------------------------------------------------------------------
template<int D, bool TWO, bool RELU, typename OutT>
__global__ __launch_bounds__(256)
void spmm_csr(const __half* __restrict__ featA, const int* __restrict__ ptrA,
              const int* __restrict__ srcA, const int* __restrict__ cntA,
              const float* __restrict__ rsqOutA, const float* __restrict__ biasA,
              const __half* __restrict__ featB, const int* __restrict__ ptrB,
              const int* __restrict__ srcB, const int* __restrict__ cntB,
              const float* __restrict__ rsqOutB, const float* __restrict__ biasB,
              OutT* __restrict__ out, int rowBeg, int rowEnd)
{
    int r = rowBeg + ((blockIdx.x * blockDim.x + threadIdx.x) >> 5);
    if (r >= rowEnd) return;
    const int lane = threadIdx.x & 31;
    constexpr int H = D / 32;

    float res[H];
    {
        int end = __ldg(&ptrA[r]);
        int cnt = __ldg(&cntA[r]);
        float acc[H];
        #pragma unroll
        for (int h = 0; h < H; h++) acc[h] = 0.f;
        gather_rel<H>(featA, srcA, rsqOutA, end - cnt, end, lane, acc);
        float ri = rsqrtf(fmaxf((float)cnt, 1.0f));
        #pragma unroll
        for (int h = 0; h < H; h++)
            res[h] = acc[h] * ri + __ldg(&biasA[lane * H + h]);
    }
    if (TWO) {
        int end = __ldg(&ptrB[r]);
        int cnt = __ldg(&cntB[r]);
        float acc[H];
        #pragma unroll
        for (int h = 0; h < H; h++) acc[h] = 0.f;
        gather_rel<H>(featB, srcB, rsqOutB, end - cnt, end, lane, acc);
        float ri = rsqrtf(fmaxf((float)cnt, 1.0f));
        #pragma unroll
        for (int h = 0; h < H; h++)
            res[h] = 0.5f * (res[h] + acc[h] * ri + __ldg(&biasB[lane * H + h]));
    }

    #pragma unroll
    for (int h = 0; h < H; h++)
        if (RELU) res[h] = fmaxf(res[h], 0.f);

    if constexpr (sizeof(OutT) == 2) {
        __half* op = (__half*)out + (size_t)r * D + lane * H;
        uint32_t pk[H / 2];
        #pragma unroll
        for (int h2 = 0; h2 < H / 2; h2++) {
            __half2 h = __floats2half2_rn(res[2 * h2], res[2 * h2 + 1]);
            pk[h2] = *(uint32_t*)&h;
        }
        if (H == 8) {
            uint4 u; u.x = pk[0]; u.y = pk[1]; u.z = pk[2]; u.w = pk[3];
            *(uint4*)op = u;
        } else {
            uint2 u; u.x = pk[0]; u.y = pk[1];
            *(uint2*)op = u;
        }
    } else {
        float* op = (float*)out + (size_t)r * D + lane * H;
        #pragma unroll
        for (int h4 = 0; h4 < H; h4 += 4)
            *(float4*)(op + h4) = make_float4(res[h4], res[h4+1], res[h4+2], res[h4+3]);
    }
}

// ---------------------------------------------------------------------------
// Launch
// ---------------------------------------------------------------------------
extern "C" void kernel_launch(void* const* d_in, const int* in_sizes, int n_in,
                              void* d_out, int out_size)
{
    const float* x_user = (const float*)d_in[0];
    const float* x_item = (const float*)d_in[1];
    const float* W1f  = (const float*)d_in[2];  const float* b1f  = (const float*)d_in[3];
    const float* W1r  = (const float*)d_in[4];  const float* b1r  = (const float*)d_in[5];
    const float* W1rb = (const float*)d_in[6];  const float* b1rb = (const float*)d_in[7];
    const float* W2f  = (const float*)d_in[8];  const float* b2f  = (const float*)d_in[9];
    const float* W2r  = (const float*)d_in[10]; const float* b2r  = (const float*)d_in[11];
    const float* W2rb = (const float*)d_in[12]; const float* b2rb = (const float*)d_in[13];
    const int* srcF  = (const int*)d_in[14]; const int* dstF  = (const int*)d_in[15];
    const int* srcR  = (const int*)d_in[16]; const int* dstR  = (const int*)d_in[17];
    const int* srcRB = (const int*)d_in[18]; const int* dstRB = (const int*)d_in[19];
    float* out = (float*)d_out;

    const int NU = in_sizes[0] / DIN;
    const int NI = in_sizes[1] / DIN;
    const int E  = in_sizes[14];

    __half *p_featA, *p_featB, *p_featC, *p_f2A, *p_f2B, *p_f2C;
    __half *p_hu, *p_hi, *p_xu, *p_xi, *p_w;
    float *p_rsq;
    int *p_deg, *p_ptr, *p_src;
    cudaGetSymbolAddress((void**)&p_featA, g_featA);
    cudaGetSymbolAddress((void**)&p_featB, g_featB);
    cudaGetSymbolAddress((void**)&p_featC, g_featC);
    cudaGetSymbolAddress((void**)&p_f2A,   g_feat2A);
    cudaGetSymbolAddress((void**)&p_f2B,   g_feat2B);
    cudaGetSymbolAddress((void**)&p_f2C,   g_feat2C);
    cudaGetSymbolAddress((void**)&p_hu,    g_hu16);
    cudaGetSymbolAddress((void**)&p_hi,    g_hi16);
    cudaGetSymbolAddress((void**)&p_xu,    g_xu16);
    cudaGetSymbolAddress((void**)&p_xi,    g_xi16);
    cudaGetSymbolAddress((void**)&p_w,     g_w16);
    cudaGetSymbolAddress((void**)&p_deg,   g_deg);
    cudaGetSymbolAddress((void**)&p_rsq,   g_rsq);
    cudaGetSymbolAddress((void**)&p_ptr,   g_csr_ptr);
    cudaGetSymbolAddress((void**)&p_src,   g_csr_src);

    const int GEMM_SMEM = (2 * 128 * 72 + 2 * 64 * 72) * (int)sizeof(__half);
    cudaFuncSetAttribute(gemm_f16<DHID>, cudaFuncAttributeMaxDynamicSharedMemorySize, GEMM_SMEM);
    cudaFuncSetAttribute(gemm_f16<DOUT>, cudaFuncAttributeMaxDynamicSharedMemorySize, GEMM_SMEM);

    const int TB = 256;
    const int eGrid = (E + TB - 1) / TB;
    const int x4u = NU * DIN / 4, x4i = NI * DIN / 4;
    const int w256Grid = (256 * 256 + TB - 1) / TB;
    const int w128Grid = (128 * 256 + TB - 1) / TB;

    // row halves (128-aligned for clean GEMM tiles)
    int NUa = ((NU / 2 + 127) / 128) * 128; if (NUa > NU) NUa = NU;
    int NIa = ((NI / 2 + 127) / 128) * 128; if (NIa > NI) NIa = NI;

    dim3 g256u((NU + 127) / 128, DHID / 64);
    dim3 g256i((NI + 127) / 128, DHID / 64);
    dim3 gU0((NUa + 127) / 128, DOUT / 64);
    dim3 gU1((NU - NUa + 127) / 128, DOUT / 64);
    dim3 gI0((NIa + 127) / 128, DOUT / 64);
    dim3 gI1((NI - NIa + 127) / 128, DOUT / 64);

    auto spmmGrid = [&](int rows) { return (rows * 32 + TB - 1) / TB; };

    Ctx& c = g_ctx;

    // ---- fork root ----
    cudaEventRecord(c.evRoot, 0);
    cudaStreamWaitEvent(c.sC, c.evRoot, 0);
    cudaStreamWaitEvent(c.s1, c.evRoot, 0);
    cudaStreamWaitEvent(c.s2, c.evRoot, 0);
    cudaStreamWaitEvent(c.s3, c.evRoot, 0);

    // ---- sC (low prio): CSR head ----
    cudaMemsetAsync(p_deg, 0, 6 * NMAX * sizeof(int), c.sC);
    deg3_kernel<<<eGrid, TB, 0, c.sC>>>(srcF, dstF, srcR, dstR, srcRB, dstRB, p_deg, E);
    cudaEventRecord(c.evDeg, c.sC);
    scan3_kernel<<<3, 1024, 0, c.sC>>>(p_deg, p_ptr);
    cudaEventRecord(c.evScan, c.sC);
    place_kernel<<<eGrid, TB, 0, c.sC>>>(srcF, dstF, p_ptr + 0 * NMAX, p_src + 0 * EMAX, E);
    cudaEventRecord(c.evPF, c.sC);
    place_kernel<<<eGrid, TB, 0, c.sC>>>(srcR, dstR, p_ptr + 1 * NMAX, p_src + 1 * EMAX, E);
    cudaEventRecord(c.evPR, c.sC);

    // ---- s3 (low prio): rsq + placeRB (evPRB implies rsq done) ----
    cudaStreamWaitEvent(c.s3, c.evDeg, 0);
    rsq_kernel<<<(6 * NMAX + TB - 1) / TB, TB, 0, c.s3>>>(p_deg, p_rsq, 6 * NMAX);
    cudaStreamWaitEvent(c.s3, c.evScan, 0);
    place_kernel<<<eGrid, TB, 0, c.s3>>>(srcRB, dstRB, p_ptr + 2 * NMAX, p_src + 2 * EMAX, E);
    cudaEventRecord(c.evPRB, c.s3);

    // ---- stream 0: W1f + x_user -> G1f ----
    cvtW_kernel<256><<<w256Grid, TB, 0, 0>>>(W1f, p_w + W16_1F);
    cvtX_kernel<<<(x4u + TB - 1) / TB, TB, 0, 0>>>(x_user, p_xu, x4u);
    cudaEventRecord(c.evXU, 0);
    gemm_f16<DHID><<<g256u, TB, GEMM_SMEM, 0>>>(p_xu, p_w + W16_1F, p_featA, NU);
    cudaEventRecord(c.evG1f, 0);

    // ---- s1 (high prio): W1rb + x_item -> G1rb ----
    cvtW_kernel<256><<<w256Grid, TB, 0, c.s1>>>(W1rb, p_w + W16_1RB);
    cvtX_kernel<<<(x4i + TB - 1) / TB, TB, 0, c.s1>>>(x_item, p_xi, x4i);
    gemm_f16<DHID><<<g256i, TB, GEMM_SMEM, c.s1>>>(p_xi, p_w + W16_1RB, p_featB, NI);

    // ---- s2 (high prio): W1r + layer-2 weights -> G1r ----
    cvtW_kernel<256><<<w256Grid, TB, 0, c.s2>>>(W1r, p_w + W16_1R);
    cvtW_kernel<128><<<w128Grid, TB, 0, c.s2>>>(W2f,  p_w + W16_2F);
    cvtW_kernel<128><<<w128Grid, TB, 0, c.s2>>>(W2r,  p_w + W16_2R);
    cvtW_kernel<128><<<w128Grid, TB, 0, c.s2>>>(W2rb, p_w + W16_2RB);
    cudaEventRecord(c.evW2, c.s2);
    cudaStreamWaitEvent(c.s2, c.evXU, 0);
    gemm_f16<DHID><<<g256u, TB, GEMM_SMEM, c.s2>>>(p_xu, p_w + W16_1R, p_featC, NU);

    // ---- spmmU1 on s1 in TWO row-halves ----
    cudaStreamWaitEvent(c.s1, c.evG1f, 0);
    cudaStreamWaitEvent(c.s1, c.evPF, 0);
    cudaStreamWaitEvent(c.s1, c.evPRB, 0);
    spmm_csr<DHID, true, true, __half><<<spmmGrid(NUa), TB, 0, c.s1>>>(
        p_featA, p_ptr + 0 * NMAX, p_src + 0 * EMAX, p_deg + 1 * NMAX,
        p_rsq + 0 * NMAX, b1f,
        p_featB, p_ptr + 2 * NMAX, p_src + 2 * EMAX, p_deg + 5 * NMAX,
        p_rsq + 4 * NMAX, b1rb,
        p_hu, 0, NUa);
    cudaEventRecord(c.evHU0, c.s1);
    spmm_csr<DHID, true, true, __half><<<spmmGrid(NU - NUa), TB, 0, c.s1>>>(
        p_featA, p_ptr + 0 * NMAX, p_src + 0 * EMAX, p_deg + 1 * NMAX,
        p_rsq + 0 * NMAX, b1f,
        p_featB, p_ptr + 2 * NMAX, p_src + 2 * EMAX, p_deg + 5 * NMAX,
        p_rsq + 4 * NMAX, b1rb,
        p_hu, NUa, NU);
    cudaEventRecord(c.evHU1, c.s1);

    // ---- spmmI1 on s2 in TWO row-halves ----
    cudaStreamWaitEvent(c.s2, c.evPR, 0);
    cudaStreamWaitEvent(c.s2, c.evPRB, 0);
    spmm_csr<DHID, false, true, __half><<<spmmGrid(NIa), TB, 0, c.s2>>>(
        p_featC, p_ptr + 1 * NMAX, p_src + 1 * EMAX, p_deg + 3 * NMAX,
        p_rsq + 2 * NMAX, b1r,
        nullptr, nullptr, nullptr, nullptr, nullptr, nullptr,
        p_hi, 0, NIa);
    cudaEventRecord(c.evHI0, c.s2);
    spmm_csr<DHID, false, true, __half><<<spmmGrid(NI - NIa), TB, 0, c.s2>>>(
        p_featC, p_ptr + 1 * NMAX, p_src + 1 * EMAX, p_deg + 3 * NMAX,
        p_rsq + 2 * NMAX, b1r,
        nullptr, nullptr, nullptr, nullptr, nullptr, nullptr,
        p_hi, NIa, NI);
    cudaEventRecord(c.evHI1, c.s2);

    // ---- layer-2 GEMMs, chunked ----
    cudaStreamWaitEvent(0, c.evHU0, 0);
    cudaStreamWaitEvent(0, c.evW2, 0);
    gemm_f16<DOUT><<<gU0, TB, GEMM_SMEM, 0>>>(p_hu, p_w + W16_2F, p_f2A, NUa);
    cudaStreamWaitEvent(0, c.evHU1, 0);
    gemm_f16<DOUT><<<gU1, TB, GEMM_SMEM, 0>>>(p_hu + (size_t)NUa * DHID, p_w + W16_2F,
                                              p_f2A + (size_t)NUa * DOUT, NU - NUa);
    cudaEventRecord(c.evG2f, 0);

    cudaStreamWaitEvent(c.s1, c.evHI0, 0);
    cudaStreamWaitEvent(c.s1, c.evW2, 0);
    gemm_f16<DOUT><<<gI0, TB, GEMM_SMEM, c.s1>>>(p_hi, p_w + W16_2RB, p_f2B, NIa);
    cudaStreamWaitEvent(c.s1, c.evHI1, 0);
    gemm_f16<DOUT><<<gI1, TB, GEMM_SMEM, c.s1>>>(p_hi + (size_t)NIa * DHID, p_w + W16_2RB,
                                                 p_f2B + (size_t)NIa * DOUT, NI - NIa);

    cudaStreamWaitEvent(c.s2, c.evHU0, 0);
    gemm_f16<DOUT><<<gU0, TB, GEMM_SMEM, c.s2>>>(p_hu, p_w + W16_2R, p_f2C, NUa);
    cudaStreamWaitEvent(c.s2, c.evHU1, 0);
    gemm_f16<DOUT><<<gU1, TB, GEMM_SMEM, c.s2>>>(p_hu + (size_t)NUa * DHID, p_w + W16_2R,
                                                 p_f2C + (size_t)NUa * DOUT, NU - NUa);

    // ---- spmmU2 on s1, wait G2f ----
    cudaStreamWaitEvent(c.s1, c.evG2f, 0);
    spmm_csr<DOUT, true, false, float><<<spmmGrid(NU), TB, 0, c.s1>>>(
        p_f2A, p_ptr + 0 * NMAX, p_src + 0 * EMAX, p_deg + 1 * NMAX,
        p_rsq + 0 * NMAX, b2f,
        p_f2B, p_ptr + 2 * NMAX, p_src + 2 * EMAX, p_deg + 5 * NMAX,
        p_rsq + 4 * NMAX, b2rb,
        out, 0, NU);
    cudaEventRecord(c.evU2, c.s1);

    // ---- spmmI2 on s2 ----
    spmm_csr<DOUT, false, false, float><<<spmmGrid(NI), TB, 0, c.s2>>>(
        p_f2C, p_ptr + 1 * NMAX, p_src + 1 * EMAX, p_deg + 3 * NMAX,
        p_rsq + 2 * NMAX, b2r,
        nullptr, nullptr, nullptr, nullptr, nullptr, nullptr,
        out + (size_t)NU * DOUT, 0, NI);
    cudaEventRecord(c.evI2, c.s2);

    // ---- join ----
    cudaStreamWaitEvent(0, c.evU2, 0);
    cudaStreamWaitEvent(0, c.evI2, 0);
}

// round 16
// speedup vs baseline: 1.1768x; 1.1768x over previous
#include <cuda_runtime.h>
#include <cuda_fp16.h>
#include <cstdint>

// ---------------------------------------------------------------------------
// Problem constants
// ---------------------------------------------------------------------------
#define NMAX 50000
#define EMAX 800000
#define DIN  256
#define DHID 256
#define DOUT 128

// ---------------------------------------------------------------------------
// Device scratch
// ---------------------------------------------------------------------------
__device__ __half g_featA[(size_t)NMAX * DHID];   // layer-1 GEMM outputs
__device__ __half g_featB[(size_t)NMAX * DHID];
__device__ __half g_featC[(size_t)NMAX * DHID];
__device__ __half g_feat2A[(size_t)NMAX * DOUT];  // layer-2 GEMM outputs
__device__ __half g_feat2B[(size_t)NMAX * DOUT];
__device__ __half g_feat2C[(size_t)NMAX * DOUT];
__device__ __half g_hu16[(size_t)NMAX * DHID];
__device__ __half g_hi16[(size_t)NMAX * DHID];
__device__ __half g_xu16[(size_t)NMAX * DIN];
__device__ __half g_xi16[(size_t)NMAX * DIN];
__device__ __half g_w16 [3 * 256 * 256 + 3 * 128 * 256];  // transposed fp16 weights
__device__ int    g_deg [6 * NMAX];   // 0/2/4: out-deg F/R/RB, 1/3/5: in-deg F/R/RB
__device__ float  g_rsq [6 * NMAX];
__device__ int    g_csr_ptr[3 * NMAX];
__device__ int    g_csr_src[3 * EMAX];

// weight slot offsets in g_w16
#define W16_1F   0
#define W16_1R   (256 * 256)
#define W16_1RB  (2 * 256 * 256)
#define W16_2F   (3 * 256 * 256)
#define W16_2R   (3 * 256 * 256 + 128 * 256)
#define W16_2RB  (3 * 256 * 256 + 2 * 128 * 256)

// ---------------------------------------------------------------------------
// Streams/events (static-init, before harness mem checkpoints)
// ---------------------------------------------------------------------------
namespace {
struct Ctx {
    cudaStream_t sC, s1, s2, s3;
    cudaEvent_t evRoot, evXU, evG1f, evDeg, evScan, evPF, evPR, evPRB,
                evW2, evHU0, evHU1, evHI0, evHI1, evG2f, evU2, evI2;
    Ctx() {
        int lo = 0, hi = 0;
        cudaDeviceGetStreamPriorityRange(&lo, &hi);
        cudaStreamCreateWithPriority(&s1, cudaStreamNonBlocking, hi);
        cudaStreamCreateWithPriority(&s2, cudaStreamNonBlocking, hi);
        cudaStreamCreateWithPriority(&sC, cudaStreamNonBlocking, lo);
        cudaStreamCreateWithPriority(&s3, cudaStreamNonBlocking, lo);
        cudaEvent_t* evs[16] = {&evRoot, &evXU, &evG1f, &evDeg, &evScan,
                                &evPF, &evPR, &evPRB, &evW2, &evHU0, &evHU1,
                                &evHI0, &evHI1, &evG2f, &evU2, &evI2};
        for (int i = 0; i < 16; i++)
            cudaEventCreateWithFlags(evs[i], cudaEventDisableTiming);
    }
};
Ctx g_ctx;
}

// ---------------------------------------------------------------------------
// fp32 -> fp16 converters
// ---------------------------------------------------------------------------
__global__ void cvtX_kernel(const float* __restrict__ in, __half* __restrict__ out, int n4)
{
    int i = blockIdx.x * blockDim.x + threadIdx.x;
    if (i < n4) {
        float4 v = ((const float4*)in)[i];
        __half2 h0 = __floats2half2_rn(v.x, v.y);
        __half2 h1 = __floats2half2_rn(v.z, v.w);
        uint2 u;
        u.x = *(uint32_t*)&h0;
        u.y = *(uint32_t*)&h1;
        ((uint2*)out)[i] = u;
    }
}

// W [256 x N_] fp32 row-major  ->  Wt [N_ x 256] fp16 (k contiguous)
template<int N_>
__global__ void cvtW_kernel(const float* __restrict__ in, __half* __restrict__ out)
{
    int i = blockIdx.x * blockDim.x + threadIdx.x;
    if (i < N_ * 256) {
        int n = i >> 8;
        int k = i & 255;
        out[i] = __float2half(in[k * N_ + n]);
    }
}

// Fused head: W (256x256, transpose+cvt) AND x (row cvt) in one launch.
__global__ void cvtWX_kernel(const float* __restrict__ W, __half* __restrict__ Wo,
                             const float* __restrict__ X, __half* __restrict__ Xo,
                             int n4)
{
    const int wElems = 256 * 256;
    int i = blockIdx.x * blockDim.x + threadIdx.x;
    if (i < wElems) {
        int n = i >> 8;
        int k = i & 255;
        Wo[i] = __float2half(W[k * 256 + n]);
    } else {
        int j = i - wElems;
        if (j < n4) {
            float4 v = ((const float4*)X)[j];
            __half2 h0 = __floats2half2_rn(v.x, v.y);
            __half2 h1 = __floats2half2_rn(v.z, v.w);
            uint2 u;
            u.x = *(uint32_t*)&h0;
            u.y = *(uint32_t*)&h1;
            ((uint2*)Xo)[j] = u;
        }
    }
}

// ---------------------------------------------------------------------------
// Degrees: all 3 relations in one pass
// ---------------------------------------------------------------------------
__global__ void deg3_kernel(const int* __restrict__ sF, const int* __restrict__ dF,
                            const int* __restrict__ sR, const int* __restrict__ dR,
                            const int* __restrict__ sRB, const int* __restrict__ dRB,
                            int* __restrict__ deg, int E)
{
    int i = blockIdx.x * blockDim.x + threadIdx.x;
    if (i < E) {
        atomicAdd(&deg[0 * NMAX + sF[i]],  1);
        atomicAdd(&deg[1 * NMAX + dF[i]],  1);
        atomicAdd(&deg[2 * NMAX + sR[i]],  1);
        atomicAdd(&deg[3 * NMAX + dR[i]],  1);
        atomicAdd(&deg[4 * NMAX + sRB[i]], 1);
        atomicAdd(&deg[5 * NMAX + dRB[i]], 1);
    }
}

__global__ void rsq_kernel(const int* __restrict__ deg, float* __restrict__ rsq, int n)
{
    int i = blockIdx.x * blockDim.x + threadIdx.x;
    if (i < n) rsq[i] = rsqrtf(fmaxf((float)deg[i], 1.0f));
}

// ---------------------------------------------------------------------------
// Exclusive scan of the 3 in-degree histograms -> csr_ptr. One block per rel.
// ---------------------------------------------------------------------------
__global__ __launch_bounds__(1024)
void scan3_kernel(const int* __restrict__ deg, int* __restrict__ csr_ptr)
{
    const int rel = blockIdx.x;
    const int* c = deg + (2 * rel + 1) * NMAX;
    int* p = csr_ptr + rel * NMAX;
    __shared__ int wtot[32];
    __shared__ int carry;
    const int tid = threadIdx.x, lane = tid & 31, wid = tid >> 5;
    if (tid == 0) carry = 0;
    __syncthreads();
    for (int base = 0; base < NMAX; base += 1024) {
        int i = base + tid;
        int v = (i < NMAX) ? c[i] : 0;
        int x = v;
        #pragma unroll
        for (int d = 1; d < 32; d <<= 1) {
            int y = __shfl_up_sync(0xffffffffu, x, d);
            if (lane >= d) x += y;
        }
        if (lane == 31) wtot[wid] = x;
        __syncthreads();
        if (wid == 0) {
            int t = wtot[lane];
            #pragma unroll
            for (int d = 1; d < 32; d <<= 1) {
                int y = __shfl_up_sync(0xffffffffu, t, d);
                if (lane >= d) t += y;
            }
            wtot[lane] = t;
        }
        __syncthreads();
        int base_w = (wid == 0) ? 0 : wtot[wid - 1];
        if (i < NMAX) p[i] = carry + base_w + x - v;
        __syncthreads();
        if (tid == 0) carry += wtot[31];
        __syncthreads();
    }
}

__global__ void place_kernel(const int* __restrict__ src, const int* __restrict__ dst,
                             int* __restrict__ ptr, int* __restrict__ outsrc, int E)
{
    int i = blockIdx.x * blockDim.x + threadIdx.x;
    if (i < E) {
        int p = atomicAdd(&ptr[dst[i]], 1);
        outsrc[p] = src[i];
    }
}

// ---------------------------------------------------------------------------
// cp.async helper (16B, zero-fill when pred false)
// ---------------------------------------------------------------------------
__device__ __forceinline__ void cp16(uint32_t saddr, const void* gptr, bool pred)
{
    int sz = pred ? 16 : 0;
    asm volatile("cp.async.ca.shared.global [%0], [%1], 16, %2;"
                 :: "r"(saddr), "l"(gptr), "r"(sz));
}

// ---------------------------------------------------------------------------
// FP16 tensor-core GEMM (fp32 accumulate), cp.async double-buffered:
//   C[M x N] (fp16) = A[M x 256] (fp16) @ Wt[N x 256]^T (fp16)
// BM=128, BN=128, BK=64; 8 warps (2M x 4N), warp tile 64x32, m16n8k16.
// Scalar LDS fragment loads (stride 72 halves, conflict-free).
// Wider BN halves per-row A re-reads vs BN=64.
// ---------------------------------------------------------------------------
template<int N>
__global__ __launch_bounds__(256)
void gemm_f16(const __half* __restrict__ A, const __half* __restrict__ Wt,
              __half* __restrict__ C, int M)
{
    constexpr int K = 256, BM = 128, BN = 128, BK = 64;
    constexpr int STR = 72;                 // halves
    constexpr int ABUF = BM * STR;
    constexpr int BBUF = BN * STR;
    extern __shared__ __half sm[];
    __half* As = sm;                        // [2][BM][STR]
    __half* Bs = sm + 2 * ABUF;             // [2][BN][STR]

    const int tid  = threadIdx.x;
    const int warp = tid >> 5;
    const int lane = tid & 31;
    const int wm = (warp >> 2) * 64;        // 2 M-groups
    const int wn = (warp & 3) * 32;         // 4 N-groups
    const int row0 = blockIdx.x * BM;
    const int col0 = blockIdx.y * BN;

    // A staging: 2 threads/row, 64B (4x16B) each
    const int arow = tid >> 1;              // 0..127
    const int aseg = (tid & 1) * 32;        // halves
    const bool aok = (row0 + arow) < M;
    const __half* agp = A + (size_t)(aok ? row0 + arow : 0) * K + aseg;
    // B staging: 2 threads/row, 64B each (BN=128 rows)
    const __half* bgp = Wt + (size_t)(col0 + arow) * K + aseg;

    auto stage = [&](int buf, int k0) {
        uint32_t as = (uint32_t)__cvta_generic_to_shared(
            &As[buf * ABUF + arow * STR + aseg]);
        const __half* ag = agp + k0;
        #pragma unroll
        for (int j = 0; j < 4; j++) cp16(as + j * 16, ag + j * 8, aok);
        uint32_t bs = (uint32_t)__cvta_generic_to_shared(
            &Bs[buf * BBUF + arow * STR + aseg]);
        const __half* bg = bgp + k0;
        #pragma unroll
        for (int j = 0; j < 4; j++) cp16(bs + j * 16, bg + j * 8, true);
    };

    stage(0, 0);
    asm volatile("cp.async.commit_group;");

    float acc[4][4][4] = {};

    #pragma unroll
    for (int t = 0; t < K / BK; t++) {
        int buf = t & 1;
        if (t + 1 < K / BK) stage(buf ^ 1, (t + 1) * BK);
        asm volatile("cp.async.commit_group;");
        asm volatile("cp.async.wait_group 1;");
        __syncthreads();

        const __half* Ab = As + buf * ABUF;
        const __half* Bb = Bs + buf * BBUF;
        #pragma unroll
        for (int ks = 0; ks < BK; ks += 16) {
            const int cA = ks + 2 * (lane & 3);
            uint32_t a[4][4];
            #pragma unroll
            for (int mt = 0; mt < 4; mt++) {
                int r = wm + mt * 16 + (lane >> 2);
                a[mt][0] = *(const uint32_t*)&Ab[(r    ) * STR + cA    ];
                a[mt][1] = *(const uint32_t*)&Ab[(r + 8) * STR + cA    ];
                a[mt][2] = *(const uint32_t*)&Ab[(r    ) * STR + cA + 8];
                a[mt][3] = *(const uint32_t*)&Ab[(r + 8) * STR + cA + 8];
            }
            uint32_t b[4][2];
            #pragma unroll
            for (int nt = 0; nt < 4; nt++) {
                int n = wn + nt * 8 + (lane >> 2);
                b[nt][0] = *(const uint32_t*)&Bb[n * STR + cA    ];
                b[nt][1] = *(const uint32_t*)&Bb[n * STR + cA + 8];
            }
            #pragma unroll
            for (int mt = 0; mt < 4; mt++)
                #pragma unroll
                for (int nt = 0; nt < 4; nt++) {
                    asm volatile(
                        "mma.sync.aligned.m16n8k16.row.col.f32.f16.f16.f32 "
                        "{%0,%1,%2,%3}, {%4,%5,%6,%7}, {%8,%9}, {%0,%1,%2,%3};"
                        : "+f"(acc[mt][nt][0]), "+f"(acc[mt][nt][1]),
                          "+f"(acc[mt][nt][2]), "+f"(acc[mt][nt][3])
                        : "r"(a[mt][0]), "r"(a[mt][1]), "r"(a[mt][2]), "r"(a[mt][3]),
                          "r"(b[nt][0]), "r"(b[nt][1]));
                }
        }
        __syncthreads();
    }

    #pragma unroll
    for (int mt = 0; mt < 4; mt++) {
        int r0g = row0 + wm + mt * 16 + (lane >> 2);
        int r1g = r0g + 8;
        #pragma unroll
        for (int nt = 0; nt < 4; nt++) {
            int cg = col0 + wn + nt * 8 + 2 * (lane & 3);
            if (r0g < M) {
                __half2 h = __floats2half2_rn(acc[mt][nt][0], acc[mt][nt][1]);
                *(__half2*)(C + (size_t)r0g * N + cg) = h;
            }
            if (r1g < M) {
                __half2 h = __floats2half2_rn(acc[mt][nt][2], acc[mt][nt][3]);
                *(__half2*)(C + (size_t)r1g * N + cg) = h;
            }
        }
    }
}

// ---------------------------------------------------------------------------
// One fp16 row accumulate
// ---------------------------------------------------------------------------
template<int H>
__device__ __forceinline__ void acc_row(const __half* __restrict__ feat,
                                        int s, float w, int lane, float acc[H])
{
    constexpr int D = H * 32;
    const __half* r = feat + (size_t)s * D + lane * H;
    if (H == 8) {
        uint4 u = __ldg((const uint4*)r);
        float2 f0 = __half22float2(*(__half2*)&u.x);
        float2 f1 = __half22float2(*(__half2*)&u.y);
        float2 f2 = __half22float2(*(__half2*)&u.z);
        float2 f3 = __half22float2(*(__half2*)&u.w);
        acc[0] += w * f0.x; acc[1] += w * f0.y;
        acc[2] += w * f1.x; acc[3] += w * f1.y;
        acc[4] += w * f2.x; acc[5] += w * f2.y;
        acc[6] += w * f3.x; acc[7] += w * f3.y;
    } else {
        uint2 u = __ldg((const uint2*)r);
        float2 f0 = __half22float2(*(__half2*)&u.x);
        float2 f1 = __half22float2(*(__half2*)&u.y);
        acc[0] += w * f0.x; acc[1] += w * f0.y;
        acc[2] += w * f1.x; acc[3] += w * f1.y;
    }
}

template<int H>
__device__ __forceinline__ void gather_rel(
    const __half* __restrict__ feat, const int* __restrict__ src,
    const float* __restrict__ rsqOut, int beg, int end, int lane, float acc[H])
{
    int e = beg;
    for (; e + 4 <= end; e += 4) {
        int s0 = __ldg(&src[e]);
        int s1 = __ldg(&src[e + 1]);
        int s2 = __ldg(&src[e + 2]);
        int s3 = __ldg(&src[e + 3]);
        float w0 = __ldg(&rsqOut[s0]);
        float w1 = __ldg(&rsqOut[s1]);
        float w2 = __ldg(&rsqOut[s2]);
        float w3 = __ldg(&rsqOut[s3]);
        acc_row<H>(feat, s0, w0, lane, acc);
        acc_row<H>(feat, s1, w1, lane, acc);
        acc_row<H>(feat, s2, w2, lane, acc);
        acc_row<H>(feat, s3, w3, lane, acc);
    }
    for (; e < end; e++) {
        int s = __ldg(&src[e]);
        float w = __ldg(&rsqOut[s]);
        acc_row<H>(feat, s, w, lane, acc);
    }
}

// ---------------------------------------------------------------------------
// Gather-SpMM (fp16 features), fused epilogue. One warp per dst row.
// Processes rows [rowBeg, rowEnd) for cross-layer chunked pipelining.
// ---------------------------------------------------------------------------
template<int D, bool TWO, bool RELU, typename OutT>
__global__ __launch_bounds__(256)
void spmm_csr(const __half* __restrict__ featA, const int* __restrict__ ptrA,
              const int* __restrict__ srcA, const int* __restrict__ cntA,
              const float* __restrict__ rsqOutA, const float* __restrict__ biasA,
              const __half* __restrict__ featB, const int* __restrict__ ptrB,
              const int* __restrict__ srcB, const int* __restrict__ cntB,
              const float* __restrict__ rsqOutB, const float* __restrict__ biasB,
              OutT* __restrict__ out, int rowBeg, int rowEnd)
{
    int r = rowBeg + ((blockIdx.x * blockDim.x + threadIdx.x) >> 5);
    if (r >= rowEnd) return;
    const int lane = threadIdx.x & 31;
    constexpr int H = D / 32;

    float res[H];
    {
        int end = __ldg(&ptrA[r]);
        int cnt = __ldg(&cntA[r]);
        float acc[H];
        #pragma unroll
        for (int h = 0; h < H; h++) acc[h] = 0.f;
        gather_rel<H>(featA, srcA, rsqOutA, end - cnt, end, lane, acc);
        float ri = rsqrtf(fmaxf((float)cnt, 1.0f));
        #pragma unroll
        for (int h = 0; h < H; h++)
            res[h] = acc[h] * ri + __ldg(&biasA[lane * H + h]);
    }
    if (TWO) {
        int end = __ldg(&ptrB[r]);
        int cnt = __ldg(&cntB[r]);
        float acc[H];
        #pragma unroll
        for (int h = 0; h < H; h++) acc[h] = 0.f;
        gather_rel<H>(featB, srcB, rsqOutB, end - cnt, end, lane, acc);
        float ri = rsqrtf(fmaxf((float)cnt, 1.0f));
        #pragma unroll
        for (int h = 0; h < H; h++)
            res[h] = 0.5f * (res[h] + acc[h] * ri + __ldg(&biasB[lane * H + h]));
    }

    #pragma unroll
    for (int h = 0; h < H; h++)
        if (RELU) res[h] = fmaxf(res[h], 0.f);

    if constexpr (sizeof(OutT) == 2) {
        __half* op = (__half*)out + (size_t)r * D + lane * H;
        uint32_t pk[H / 2];
        #pragma unroll
        for (int h2 = 0; h2 < H / 2; h2++) {
            __half2 h = __floats2half2_rn(res[2 * h2], res[2 * h2 + 1]);
            pk[h2] = *(uint32_t*)&h;
        }
        if (H == 8) {
            uint4 u; u.x = pk[0]; u.y = pk[1]; u.z = pk[2]; u.w = pk[3];
            *(uint4*)op = u;
        } else {
            uint2 u; u.x = pk[0]; u.y = pk[1];
            *(uint2*)op = u;
        }
    } else {
        float* op = (float*)out + (size_t)r * D + lane * H;
        #pragma unroll
        for (int h4 = 0; h4 < H; h4 += 4)
            *(float4*)(op + h4) = make_float4(res[h4], res[h4+1], res[h4+2], res[h4+3]);
    }
}

// ---------------------------------------------------------------------------
// Launch
// ---------------------------------------------------------------------------
extern "C" void kernel_launch(void* const* d_in, const int* in_sizes, int n_in,
                              void* d_out, int out_size)
{
    const float* x_user = (const float*)d_in[0];
    const float* x_item = (const float*)d_in[1];
    const float* W1f  = (const float*)d_in[2];  const float* b1f  = (const float*)d_in[3];
    const float* W1r  = (const float*)d_in[4];  const float* b1r  = (const float*)d_in[5];
    const float* W1rb = (const float*)d_in[6];  const float* b1rb = (const float*)d_in[7];
    const float* W2f  = (const float*)d_in[8];  const float* b2f  = (const float*)d_in[9];
    const float* W2r  = (const float*)d_in[10]; const float* b2r  = (const float*)d_in[11];
    const float* W2rb = (const float*)d_in[12]; const float* b2rb = (const float*)d_in[13];
    const int* srcF  = (const int*)d_in[14]; const int* dstF  = (const int*)d_in[15];
    const int* srcR  = (const int*)d_in[16]; const int* dstR  = (const int*)d_in[17];
    const int* srcRB = (const int*)d_in[18]; const int* dstRB = (const int*)d_in[19];
    float* out = (float*)d_out;

    const int NU = in_sizes[0] / DIN;
    const int NI = in_sizes[1] / DIN;
    const int E  = in_sizes[14];

    __half *p_featA, *p_featB, *p_featC, *p_f2A, *p_f2B, *p_f2C;
    __half *p_hu, *p_hi, *p_xu, *p_xi, *p_w;
    float *p_rsq;
    int *p_deg, *p_ptr, *p_src;
    cudaGetSymbolAddress((void**)&p_featA, g_featA);
    cudaGetSymbolAddress((void**)&p_featB, g_featB);
    cudaGetSymbolAddress((void**)&p_featC, g_featC);
    cudaGetSymbolAddress((void**)&p_f2A,   g_feat2A);
    cudaGetSymbolAddress((void**)&p_f2B,   g_feat2B);
    cudaGetSymbolAddress((void**)&p_f2C,   g_feat2C);
    cudaGetSymbolAddress((void**)&p_hu,    g_hu16);
    cudaGetSymbolAddress((void**)&p_hi,    g_hi16);
    cudaGetSymbolAddress((void**)&p_xu,    g_xu16);
    cudaGetSymbolAddress((void**)&p_xi,    g_xi16);
    cudaGetSymbolAddress((void**)&p_w,     g_w16);
    cudaGetSymbolAddress((void**)&p_deg,   g_deg);
    cudaGetSymbolAddress((void**)&p_rsq,   g_rsq);
    cudaGetSymbolAddress((void**)&p_ptr,   g_csr_ptr);
    cudaGetSymbolAddress((void**)&p_src,   g_csr_src);

    const int GEMM_SMEM = (2 * 128 * 72 + 2 * 128 * 72) * (int)sizeof(__half); // 73728 B
    cudaFuncSetAttribute(gemm_f16<DHID>, cudaFuncAttributeMaxDynamicSharedMemorySize, GEMM_SMEM);
    cudaFuncSetAttribute(gemm_f16<DOUT>, cudaFuncAttributeMaxDynamicSharedMemorySize, GEMM_SMEM);

    const int TB = 256;
    const int eGrid = (E + TB - 1) / TB;
    const int x4u = NU * DIN / 4, x4i = NI * DIN / 4;
    const int w256Grid = (256 * 256 + TB - 1) / TB;
    const int w128Grid = (128 * 256 + TB - 1) / TB;
    const int headGrid = (256 * 256 + x4u + TB - 1) / TB;

    // row halves (128-aligned for clean GEMM tiles)
    int NUa = ((NU / 2 + 127) / 128) * 128; if (NUa > NU) NUa = NU;
    int NIa = ((NI / 2 + 127) / 128) * 128; if (NIa > NI) NIa = NI;

    dim3 g256u((NU + 127) / 128, DHID / 128);
    dim3 g256i((NI + 127) / 128, DHID / 128);
    dim3 gU0((NUa + 127) / 128, DOUT / 128);
    dim3 gU1((NU - NUa + 127) / 128, DOUT / 128);
    dim3 gI0((NIa + 127) / 128, DOUT / 128);
    dim3 gI1((NI - NIa + 127) / 128, DOUT / 128);

    auto spmmGrid = [&](int rows) { return (rows * 32 + TB - 1) / TB; };

    Ctx& c = g_ctx;

    // ---- fork root ----
    cudaEventRecord(c.evRoot, 0);
    cudaStreamWaitEvent(c.sC, c.evRoot, 0);
    cudaStreamWaitEvent(c.s1, c.evRoot, 0);
    cudaStreamWaitEvent(c.s2, c.evRoot, 0);
    cudaStreamWaitEvent(c.s3, c.evRoot, 0);

    // ---- sC (low prio): CSR head ----
    cudaMemsetAsync(p_deg, 0, 6 * NMAX * sizeof(int), c.sC);
    deg3_kernel<<<eGrid, TB, 0, c.sC>>>(srcF, dstF, srcR, dstR, srcRB, dstRB, p_deg, E);
    cudaEventRecord(c.evDeg, c.sC);
    scan3_kernel<<<3, 1024, 0, c.sC>>>(p_deg, p_ptr);
    cudaEventRecord(c.evScan, c.sC);
    place_kernel<<<eGrid, TB, 0, c.sC>>>(srcF, dstF, p_ptr + 0 * NMAX, p_src + 0 * EMAX, E);
    cudaEventRecord(c.evPF, c.sC);
    place_kernel<<<eGrid, TB, 0, c.sC>>>(srcR, dstR, p_ptr + 1 * NMAX, p_src + 1 * EMAX, E);
    cudaEventRecord(c.evPR, c.sC);

    // ---- s3 (low prio): rsq + placeRB (evPRB implies rsq done) ----
    cudaStreamWaitEvent(c.s3, c.evDeg, 0);
    rsq_kernel<<<(6 * NMAX + TB - 1) / TB, TB, 0, c.s3>>>(p_deg, p_rsq, 6 * NMAX);
    cudaStreamWaitEvent(c.s3, c.evScan, 0);
    place_kernel<<<eGrid, TB, 0, c.s3>>>(srcRB, dstRB, p_ptr + 2 * NMAX, p_src + 2 * EMAX, E);
    cudaEventRecord(c.evPRB, c.s3);

    // ---- stream 0: fused (W1f + x_user) cvt -> G1f ----
    cvtWX_kernel<<<headGrid, TB, 0, 0>>>(W1f, p_w + W16_1F, x_user, p_xu, x4u);
    cudaEventRecord(c.evXU, 0);
    gemm_f16<DHID><<<g256u, TB, GEMM_SMEM, 0>>>(p_xu, p_w + W16_1F, p_featA, NU);
    cudaEventRecord(c.evG1f, 0);

    // ---- s1 (high prio): W1rb + x_item -> G1rb ----
    cvtW_kernel<256><<<w256Grid, TB, 0, c.s1>>>(W1rb, p_w + W16_1RB);
    cvtX_kernel<<<(x4i + TB - 1) / TB, TB, 0, c.s1>>>(x_item, p_xi, x4i);
    gemm_f16<DHID><<<g256i, TB, GEMM_SMEM, c.s1>>>(p_xi, p_w + W16_1RB, p_featB, NI);

    // ---- s2 (high prio): W1r + layer-2 weights -> G1r ----
    cvtW_kernel<256><<<w256Grid, TB, 0, c.s2>>>(W1r, p_w + W16_1R);
    cvtW_kernel<128><<<w128Grid, TB, 0, c.s2>>>(W2f,  p_w + W16_2F);
    cvtW_kernel<128><<<w128Grid, TB, 0, c.s2>>>(W2r,  p_w + W16_2R);
    cvtW_kernel<128><<<w128Grid, TB, 0, c.s2>>>(W2rb, p_w + W16_2RB);
    cudaEventRecord(c.evW2, c.s2);
    cudaStreamWaitEvent(c.s2, c.evXU, 0);
    gemm_f16<DHID><<<g256u, TB, GEMM_SMEM, c.s2>>>(p_xu, p_w + W16_1R, p_featC, NU);

    // ---- spmmU1 on s1 in TWO row-halves ----
    cudaStreamWaitEvent(c.s1, c.evG1f, 0);
    cudaStreamWaitEvent(c.s1, c.evPF, 0);
    cudaStreamWaitEvent(c.s1, c.evPRB, 0);
    spmm_csr<DHID, true, true, __half><<<spmmGrid(NUa), TB, 0, c.s1>>>(
        p_featA, p_ptr + 0 * NMAX, p_src + 0 * EMAX, p_deg + 1 * NMAX,
        p_rsq + 0 * NMAX, b1f,
        p_featB, p_ptr + 2 * NMAX, p_src + 2 * EMAX, p_deg + 5 * NMAX,
        p_rsq + 4 * NMAX, b1rb,
        p_hu, 0, NUa);
    cudaEventRecord(c.evHU0, c.s1);
    spmm_csr<DHID, true, true, __half><<<spmmGrid(NU - NUa), TB, 0, c.s1>>>(
        p_featA, p_ptr + 0 * NMAX, p_src + 0 * EMAX, p_deg + 1 * NMAX,
        p_rsq + 0 * NMAX, b1f,
        p_featB, p_ptr + 2 * NMAX, p_src + 2 * EMAX, p_deg + 5 * NMAX,
        p_rsq + 4 * NMAX, b1rb,
        p_hu, NUa, NU);
    cudaEventRecord(c.evHU1, c.s1);

    // ---- spmmI1 on s2 in TWO row-halves ----
    cudaStreamWaitEvent(c.s2, c.evPR, 0);
    cudaStreamWaitEvent(c.s2, c.evPRB, 0);
    spmm_csr<DHID, false, true, __half><<<spmmGrid(NIa), TB, 0, c.s2>>>(
        p_featC, p_ptr + 1 * NMAX, p_src + 1 * EMAX, p_deg + 3 * NMAX,
        p_rsq + 2 * NMAX, b1r,
        nullptr, nullptr, nullptr, nullptr, nullptr, nullptr,
        p_hi, 0, NIa);
    cudaEventRecord(c.evHI0, c.s2);
    spmm_csr<DHID, false, true, __half><<<spmmGrid(NI - NIa), TB, 0, c.s2>>>(
        p_featC, p_ptr + 1 * NMAX, p_src + 1 * EMAX, p_deg + 3 * NMAX,
        p_rsq + 2 * NMAX, b1r,
        nullptr, nullptr, nullptr, nullptr, nullptr, nullptr,
        p_hi, NIa, NI);
    cudaEventRecord(c.evHI1, c.s2);

    // ---- layer-2 GEMMs, chunked ----
    cudaStreamWaitEvent(0, c.evHU0, 0);
    cudaStreamWaitEvent(0, c.evW2, 0);
    gemm_f16<DOUT><<<gU0, TB, GEMM_SMEM, 0>>>(p_hu, p_w + W16_2F, p_f2A, NUa);
    cudaStreamWaitEvent(0, c.evHU1, 0);
    gemm_f16<DOUT><<<gU1, TB, GEMM_SMEM, 0>>>(p_hu + (size_t)NUa * DHID, p_w + W16_2F,
                                              p_f2A + (size_t)NUa * DOUT, NU - NUa);
    cudaEventRecord(c.evG2f, 0);

    cudaStreamWaitEvent(c.s1, c.evHI0, 0);
    cudaStreamWaitEvent(c.s1, c.evW2, 0);
    gemm_f16<DOUT><<<gI0, TB, GEMM_SMEM, c.s1>>>(p_hi, p_w + W16_2RB, p_f2B, NIa);
    cudaStreamWaitEvent(c.s1, c.evHI1, 0);
    gemm_f16<DOUT><<<gI1, TB, GEMM_SMEM, c.s1>>>(p_hi + (size_t)NIa * DHID, p_w + W16_2RB,
                                                 p_f2B + (size_t)NIa * DOUT, NI - NIa);

    cudaStreamWaitEvent(c.s2, c.evHU0, 0);
    gemm_f16<DOUT><<<gU0, TB, GEMM_SMEM, c.s2>>>(p_hu, p_w + W16_2R, p_f2C, NUa);
    cudaStreamWaitEvent(c.s2, c.evHU1, 0);
    gemm_f16<DOUT><<<gU1, TB, GEMM_SMEM, c.s2>>>(p_hu + (size_t)NUa * DHID, p_w + W16_2R,
                                                 p_f2C + (size_t)NUa * DOUT, NU - NUa);

    // ---- spmmU2 on s1, wait G2f ----
    cudaStreamWaitEvent(c.s1, c.evG2f, 0);
    spmm_csr<DOUT, true, false, float><<<spmmGrid(NU), TB, 0, c.s1>>>(
        p_f2A, p_ptr + 0 * NMAX, p_src + 0 * EMAX, p_deg + 1 * NMAX,
        p_rsq + 0 * NMAX, b2f,
        p_f2B, p_ptr + 2 * NMAX, p_src + 2 * EMAX, p_deg + 5 * NMAX,
        p_rsq + 4 * NMAX, b2rb,
        out, 0, NU);
    cudaEventRecord(c.evU2, c.s1);

    // ---- spmmI2 on s2 ----
    spmm_csr<DOUT, false, false, float><<<spmmGrid(NI), TB, 0, c.s2>>>(
        p_f2C, p_ptr + 1 * NMAX, p_src + 1 * EMAX, p_deg + 3 * NMAX,
        p_rsq + 2 * NMAX, b2r,
        nullptr, nullptr, nullptr, nullptr, nullptr, nullptr,
        out + (size_t)NU * DOUT, 0, NI);
    cudaEventRecord(c.evI2, c.s2);

    // ---- join ----
    cudaStreamWaitEvent(0, c.evU2, 0);
    cudaStreamWaitEvent(0, c.evI2, 0);
}